// round 15
// baseline (speedup 1.0000x reference)
#include <cuda_runtime.h>
#include <cstdint>

#define BB 2
#define CC 256
#define HH 128
#define WW 128
#define H2 256
#define W2 256
#define PLANE (HH * WW)

#define CPG 32        // channels per carafe block (measured-best; CPG=64 regressed)
#define STAGE 4
#define NS (CPG / STAGE)
#define RSTR 132      // padded smem row stride (floats)
#define CHS (4 * RSTR + 4)

#define MG 32         // mean partial groups (planar layout, 8 ch each)

// scratch (no allocations allowed)
__device__ float g_part[BB * MG * PLANE];   // [b][group][pixel]  (planar)
__device__ float g_kern[BB * 9 * H2 * W2];

typedef unsigned long long ull;

// ---------------------------------------------------------------------------
// cp.async helpers
// ---------------------------------------------------------------------------
__device__ __forceinline__ void cp_async16(uint32_t dst_smem, const void* src, int src_sz) {
    asm volatile("cp.async.cg.shared.global [%0], [%1], 16, %2;\n"
                 :: "r"(dst_smem), "l"(src), "r"(src_sz));
}
__device__ __forceinline__ void cp_commit() {
    asm volatile("cp.async.commit_group;\n");
}
template <int N>
__device__ __forceinline__ void cp_wait() {
    asm volatile("cp.async.wait_group %0;\n" :: "n"(N));
}

// ---------------------------------------------------------------------------
// Kernel A: partial channel sums, PLANAR layout g_part[b][group][pixel].
// __launch_bounds__(256,4) -> 64-reg budget so all 8 LDG.128 front-batch
// (at 32 regs ptxas serialized them into load-add chains, MLP_eff ~2).
// Two-phase: load all 8 float4, then reduce.
// ---------------------------------------------------------------------------
__global__ void __launch_bounds__(256, 4) mean1_kernel(const float* __restrict__ x) {
    int t  = threadIdx.x;
    int p4 = blockIdx.x * 256 + t;          // float4-pixel [0, PLANE/4)
    int cg = blockIdx.y;                    // group [0, MG)
    int b  = blockIdx.z;
    const float4* xp = (const float4*)x
                     + (size_t)(b * CC + cg * (CC / MG)) * (PLANE / 4) + p4;
    float4 v[CC / MG];
#pragma unroll
    for (int c = 0; c < CC / MG; ++c)
        v[c] = xp[(size_t)c * (PLANE / 4)];
    float4 s = make_float4(0.f, 0.f, 0.f, 0.f);
#pragma unroll
    for (int c = 0; c < CC / MG; ++c) {
        s.x += v[c].x; s.y += v[c].y; s.z += v[c].z; s.w += v[c].w;
    }
    ((float4*)g_part)[((size_t)(b * MG + cg)) * (PLANE / 4) + p4] = s;
}

// ---------------------------------------------------------------------------
// Kernel B (fused 32-way mean-combine + kernel-field):
// Block = 16x16 output tile, 256 threads. Overlapping init ranges.
// ---------------------------------------------------------------------------
__device__ __forceinline__ float fast_tanh(float x) {
    float e = __expf(2.0f * x);
    return __fdividef(e - 1.0f, e + 1.0f);
}

__global__ void __launch_bounds__(256)
kern_kernel(const float* __restrict__ Woff, const float* __restrict__ boff) {
    __shared__ float KW[2][2][2][9];   // [ch][pi][pj][di*3+dj]
    __shared__ float sb[2];
    __shared__ float smp[200];         // per-half partial sums
    __shared__ float sm[100];          // 10x10 mean tile

    int t  = threadIdx.x;
    int b  = blockIdx.z;
    int x0 = blockIdx.x * 16;
    int y0 = blockIdx.y * 16;

    if (t < 2) sb[t] = boff[t];

    if (t < 72) {
        int ch  = t / 36, rem = t % 36;
        int pi  = rem / 18, pj = (rem / 9) & 1, k = rem % 9;
        int di  = k / 3, dj = k % 3;
        int us  = pi == 0 ? di * 2 : (di == 0 ? 0 : di * 2 - 1);
        int uc  = pi == 0 ? (di < 2 ? 2 : 1) : (di == 0 ? 1 : 2);
        int vs  = pj == 0 ? dj * 2 : (dj == 0 ? 0 : dj * 2 - 1);
        int vc  = pj == 0 ? (dj < 2 ? 2 : 1) : (dj == 0 ? 1 : 2);
        float s = 0.f;
        for (int u = 0; u < uc; ++u)
            for (int v = 0; v < vc; ++v)
                s += Woff[ch * 25 + (us + u) * 5 + (vs + v)];
        KW[ch][pi][pj][k] = s;
    }

    int hh0 = (y0 >> 1) - 1;
    int ww0 = (x0 >> 1) - 1;
    if (t < 200) {
        int cell = t >> 1;
        int half = t & 1;
        int hn = hh0 + cell / 10;
        int wn = ww0 + cell % 10;
        float s = 0.f;
        if (hn >= 0 && hn < HH && wn >= 0 && wn < WW) {
            const float* pp = g_part + ((size_t)b * MG + half * 16) * PLANE
                            + hn * WW + wn;
            float acc[4] = {0.f, 0.f, 0.f, 0.f};
#pragma unroll
            for (int g = 0; g < 16; ++g)
                acc[g & 3] += pp[(size_t)g * PLANE];
            s = (acc[0] + acc[1]) + (acc[2] + acc[3]);
        }
        smp[t] = s;
    }
    __syncthreads();
    if (t < 100)
        sm[t] = (smp[2 * t] + smp[2 * t + 1]) * (1.0f / CC);
    __syncthreads();

    int tx = t & 15, ty = t >> 4;
    int xq = x0 + tx, y = y0 + ty;
    int pi = y & 1, pj = xq & 1;
    int lh = (ty >> 1) + 1;
    int lw = (tx >> 1) + 1;

    float m3[9];
#pragma unroll
    for (int di = 0; di < 3; ++di)
#pragma unroll
        for (int dj = 0; dj < 3; ++dj)
            m3[di * 3 + dj] = sm[(lh - 1 + di) * 10 + (lw - 1 + dj)];

    const float* kw0 = KW[0][pi][pj];
    const float* kw1 = KW[1][pi][pj];
    float a0 = 0.f, a1 = 0.f;
#pragma unroll
    for (int k = 0; k < 9; ++k) {
        a0 = fmaf(m3[k], kw0[k], a0);
        a1 = fmaf(m3[k], kw1[k], a1);
    }
    float s0 = (pj ? 0.25f : -0.25f) + 0.25f * fast_tanh(a0 + sb[0]);
    float s1 = (pi ? 0.25f : -0.25f) + 0.25f * fast_tanh(a1 + sb[1]);

    float mc = m3[4];
    float ev[9];
    float sum = 0.f;
#pragma unroll
    for (int k = 0; k < 9; ++k) {
        int di = k / 3 - 1;
        int dj = k % 3 - 1;
        float d  = m3[k] - mc;
        float e0 = s0 - (float)dj;
        float e1 = s1 - (float)di;
        float d2 = fmaf(e0, e0, fmaf(e1, e1, 0.2f));
        float kv = __fdividef(1.f, fmaf(d, d, 1.f) * d2);
        ev[k] = __expf(kv);
        sum += ev[k];
    }
    float inv = __fdividef(1.f, sum);
#pragma unroll
    for (int k = 0; k < 9; ++k)
        g_kern[((b * 9 + k) * H2 + y) * W2 + xq] = ev[k] * inv;
}

// ---------------------------------------------------------------------------
// Kernel C: CARAFE apply (measured-best config: CPG=32, R3 pipeline,
// .cs output stores keeping x/g_kern L2-resident).
// ---------------------------------------------------------------------------
__global__ void __launch_bounds__(256, 4)
carafe_kernel(const float* __restrict__ x, float* __restrict__ out) {
    __shared__ __align__(16) float xs[2][STAGE][CHS];

    int b  = blockIdx.z;
    int h0 = blockIdx.y * 2;
    int c0 = blockIdx.x * CPG;
    int t  = threadIdx.x;
    int r  = t >> 7;
    int w  = t & 127;
    int h  = h0 + r;

    const ull* kp = (const ull*)(g_kern + (size_t)b * 9 * H2 * W2);
    ull wk0[9], wk1[9];
#pragma unroll
    for (int k = 0; k < 9; ++k) {
        wk0[k] = kp[((size_t)k * H2 + 2 * h)     * (W2 / 2) + w];
        wk1[k] = kp[((size_t)k * H2 + 2 * h + 1) * (W2 / 2) + w];
    }

    if (t < 64) {
        int bufi = t >> 5, lt = t & 31;
        int ch = lt >> 3, rem = lt & 7, row = rem >> 1, side = rem & 1;
        xs[bufi][ch][row * RSTR + (side ? RSTR : 3)] = 0.f;
    }

    const float* xb = x + (size_t)b * CC * PLANE;

    auto load_stage = [&](int s, int buf) {
        int cb = c0 + s * STAGE;
#pragma unroll
        for (int u = 0; u < 2; ++u) {
            int lin  = u * 256 + t;
            int ch   = lin >> 7;
            int rem  = lin & 127;
            int row  = rem >> 5;
            int col4 = rem & 31;
            int grow = h0 - 1 + row;
            int ok   = (grow >= 0 && grow < HH);
            const float* src = xb + (size_t)(cb + ch) * PLANE
                             + (ok ? grow : 0) * WW + (col4 << 2);
            uint32_t dst = (uint32_t)__cvta_generic_to_shared(
                &xs[buf][ch][row * RSTR + 4 + (col4 << 2)]);
            cp_async16(dst, src, ok ? 16 : 0);
        }
    };

    load_stage(0, 0);
    cp_commit();

#pragma unroll 1
    for (int s = 0; s < NS; ++s) {
        int buf = s & 1;
        __syncthreads();
        if (s + 1 < NS) { load_stage(s + 1, buf ^ 1); cp_commit(); cp_wait<1>(); }
        else           { cp_wait<0>(); }
        __syncthreads();

        int cbase = c0 + s * STAGE;
#pragma unroll
        for (int ch = 0; ch < STAGE; ++ch) {
            const float* base = &xs[buf][ch][r * RSTR + 4 + w];
            ull acc0 = 0ull, acc1 = 0ull;
#pragma unroll
            for (int di = 0; di < 3; ++di) {
                const float* rp = base + di * RSTR;
                float xv[3] = { rp[-1], rp[0], rp[1] };
#pragma unroll
                for (int dj = 0; dj < 3; ++dj) {
                    int k = di * 3 + dj;
                    unsigned vu = __float_as_uint(xv[dj]);
                    ull vv;
                    asm("mov.b64 %0, {%1, %2};" : "=l"(vv) : "r"(vu), "r"(vu));
                    asm("fma.rn.f32x2 %0, %1, %2, %0;"
                        : "+l"(acc0) : "l"(wk0[k]), "l"(vv));
                    asm("fma.rn.f32x2 %0, %1, %2, %0;"
                        : "+l"(acc1) : "l"(wk1[k]), "l"(vv));
                }
            }
            float2* op = (float2*)(out + (((size_t)(b * CC + cbase + ch)) * H2
                                          + 2 * h) * W2);
            __stcs(&op[w], *(float2*)&acc0);
            __stcs(&op[(W2 / 2) + w], *(float2*)&acc1);
        }
    }
}

extern "C" void kernel_launch(void* const* d_in, const int* in_sizes, int n_in,
                              void* d_out, int out_size) {
    const float* x    = (const float*)d_in[0];
    const float* Woff = (const float*)d_in[1];
    const float* boff = (const float*)d_in[2];
    float* out = (float*)d_out;

    mean1_kernel<<<dim3(PLANE / 4 / 256, MG, BB), 256>>>(x);
    kern_kernel<<<dim3(W2 / 16, H2 / 16, BB), 256>>>(Woff, boff);
    carafe_kernel<<<dim3(CC / CPG, HH / 2, BB), 256>>>(x, out);
}

// round 16
// speedup vs baseline: 1.2209x; 1.2209x over previous
#include <cuda_runtime.h>
#include <cstdint>

#define BB 2
#define CC 256
#define HH 128
#define WW 128
#define H2 256
#define W2 256
#define PLANE (HH * WW)

#define CPG 32        // channels per carafe block (measured-best config)
#define STAGE 4
#define NS (CPG / STAGE)
#define RSTR 132      // padded smem row stride (floats)
#define CHS (4 * RSTR + 4)

#define MG 32         // mean partial groups (planar layout, 8 ch each)

// scratch (no allocations allowed)
__device__ float g_part[BB * MG * PLANE];   // [b][group][pixel]  (planar)
__device__ float g_kern[BB * 9 * H2 * W2];

typedef unsigned long long ull;

// ---------------------------------------------------------------------------
// cp.async helpers
// ---------------------------------------------------------------------------
__device__ __forceinline__ void cp_async16(uint32_t dst_smem, const void* src, int src_sz) {
    asm volatile("cp.async.cg.shared.global [%0], [%1], 16, %2;\n"
                 :: "r"(dst_smem), "l"(src), "r"(src_sz));
}
__device__ __forceinline__ void cp_commit() {
    asm volatile("cp.async.commit_group;\n");
}
template <int N>
__device__ __forceinline__ void cp_wait() {
    asm volatile("cp.async.wait_group %0;\n" :: "n"(N));
}

// ---------------------------------------------------------------------------
// Kernel A: partial channel sums, PLANAR layout g_part[b][group][pixel].
// Simple accumulate loop (32 regs, occ 74%) — measured better than the
// front-batched 40-reg variant. x left L2-resident for carafe's re-read.
// ---------------------------------------------------------------------------
__global__ void mean1_kernel(const float* __restrict__ x) {
    int t  = threadIdx.x;
    int p4 = blockIdx.x * 256 + t;          // float4-pixel [0, PLANE/4)
    int cg = blockIdx.y;                    // group [0, MG)
    int b  = blockIdx.z;
    const float4* xp = (const float4*)x
                     + (size_t)(b * CC + cg * (CC / MG)) * (PLANE / 4) + p4;
    float4 s = make_float4(0.f, 0.f, 0.f, 0.f);
#pragma unroll
    for (int c = 0; c < CC / MG; ++c) {
        float4 v = xp[(size_t)c * (PLANE / 4)];
        s.x += v.x; s.y += v.y; s.z += v.z; s.w += v.w;
    }
    ((float4*)g_part)[((size_t)(b * MG + cg)) * (PLANE / 4) + p4] = s;
}

// ---------------------------------------------------------------------------
// Kernel B (fused 32-way mean-combine + kernel-field):
// Block = 16x16 output tile, 256 threads. Overlapping init ranges.
// ---------------------------------------------------------------------------
__device__ __forceinline__ float fast_tanh(float x) {
    float e = __expf(2.0f * x);
    return __fdividef(e - 1.0f, e + 1.0f);
}

__global__ void __launch_bounds__(256)
kern_kernel(const float* __restrict__ Woff, const float* __restrict__ boff) {
    __shared__ float KW[2][2][2][9];   // [ch][pi][pj][di*3+dj]
    __shared__ float sb[2];
    __shared__ float smp[200];         // per-half partial sums
    __shared__ float sm[100];          // 10x10 mean tile

    int t  = threadIdx.x;
    int b  = blockIdx.z;
    int x0 = blockIdx.x * 16;
    int y0 = blockIdx.y * 16;

    if (t < 2) sb[t] = boff[t];

    if (t < 72) {
        int ch  = t / 36, rem = t % 36;
        int pi  = rem / 18, pj = (rem / 9) & 1, k = rem % 9;
        int di  = k / 3, dj = k % 3;
        int us  = pi == 0 ? di * 2 : (di == 0 ? 0 : di * 2 - 1);
        int uc  = pi == 0 ? (di < 2 ? 2 : 1) : (di == 0 ? 1 : 2);
        int vs  = pj == 0 ? dj * 2 : (dj == 0 ? 0 : dj * 2 - 1);
        int vc  = pj == 0 ? (dj < 2 ? 2 : 1) : (dj == 0 ? 1 : 2);
        float s = 0.f;
        for (int u = 0; u < uc; ++u)
            for (int v = 0; v < vc; ++v)
                s += Woff[ch * 25 + (us + u) * 5 + (vs + v)];
        KW[ch][pi][pj][k] = s;
    }

    int hh0 = (y0 >> 1) - 1;
    int ww0 = (x0 >> 1) - 1;
    if (t < 200) {
        int cell = t >> 1;
        int half = t & 1;
        int hn = hh0 + cell / 10;
        int wn = ww0 + cell % 10;
        float s = 0.f;
        if (hn >= 0 && hn < HH && wn >= 0 && wn < WW) {
            const float* pp = g_part + ((size_t)b * MG + half * 16) * PLANE
                            + hn * WW + wn;
            float acc[4] = {0.f, 0.f, 0.f, 0.f};
#pragma unroll
            for (int g = 0; g < 16; ++g)
                acc[g & 3] += pp[(size_t)g * PLANE];
            s = (acc[0] + acc[1]) + (acc[2] + acc[3]);
        }
        smp[t] = s;
    }
    __syncthreads();
    if (t < 100)
        sm[t] = (smp[2 * t] + smp[2 * t + 1]) * (1.0f / CC);
    __syncthreads();

    int tx = t & 15, ty = t >> 4;
    int xq = x0 + tx, y = y0 + ty;
    int pi = y & 1, pj = xq & 1;
    int lh = (ty >> 1) + 1;
    int lw = (tx >> 1) + 1;

    float m3[9];
#pragma unroll
    for (int di = 0; di < 3; ++di)
#pragma unroll
        for (int dj = 0; dj < 3; ++dj)
            m3[di * 3 + dj] = sm[(lh - 1 + di) * 10 + (lw - 1 + dj)];

    const float* kw0 = KW[0][pi][pj];
    const float* kw1 = KW[1][pi][pj];
    float a0 = 0.f, a1 = 0.f;
#pragma unroll
    for (int k = 0; k < 9; ++k) {
        a0 = fmaf(m3[k], kw0[k], a0);
        a1 = fmaf(m3[k], kw1[k], a1);
    }
    float s0 = (pj ? 0.25f : -0.25f) + 0.25f * fast_tanh(a0 + sb[0]);
    float s1 = (pi ? 0.25f : -0.25f) + 0.25f * fast_tanh(a1 + sb[1]);

    float mc = m3[4];
    float ev[9];
    float sum = 0.f;
#pragma unroll
    for (int k = 0; k < 9; ++k) {
        int di = k / 3 - 1;
        int dj = k % 3 - 1;
        float d  = m3[k] - mc;
        float e0 = s0 - (float)dj;
        float e1 = s1 - (float)di;
        float d2 = fmaf(e0, e0, fmaf(e1, e1, 0.2f));
        float kv = __fdividef(1.f, fmaf(d, d, 1.f) * d2);
        ev[k] = __expf(kv);
        sum += ev[k];
    }
    float inv = __fdividef(1.f, sum);
#pragma unroll
    for (int k = 0; k < 9; ++k)
        g_kern[((b * 9 + k) * H2 + y) * W2 + xq] = ev[k] * inv;
}

// ---------------------------------------------------------------------------
// Kernel C: CARAFE apply (measured-best config: CPG=32, R3 pipeline,
// .cs output stores keeping x/g_kern L2-resident).
// ---------------------------------------------------------------------------
__global__ void __launch_bounds__(256, 4)
carafe_kernel(const float* __restrict__ x, float* __restrict__ out) {
    __shared__ __align__(16) float xs[2][STAGE][CHS];

    int b  = blockIdx.z;
    int h0 = blockIdx.y * 2;
    int c0 = blockIdx.x * CPG;
    int t  = threadIdx.x;
    int r  = t >> 7;
    int w  = t & 127;
    int h  = h0 + r;

    const ull* kp = (const ull*)(g_kern + (size_t)b * 9 * H2 * W2);
    ull wk0[9], wk1[9];
#pragma unroll
    for (int k = 0; k < 9; ++k) {
        wk0[k] = kp[((size_t)k * H2 + 2 * h)     * (W2 / 2) + w];
        wk1[k] = kp[((size_t)k * H2 + 2 * h + 1) * (W2 / 2) + w];
    }

    if (t < 64) {
        int bufi = t >> 5, lt = t & 31;
        int ch = lt >> 3, rem = lt & 7, row = rem >> 1, side = rem & 1;
        xs[bufi][ch][row * RSTR + (side ? RSTR : 3)] = 0.f;
    }

    const float* xb = x + (size_t)b * CC * PLANE;

    auto load_stage = [&](int s, int buf) {
        int cb = c0 + s * STAGE;
#pragma unroll
        for (int u = 0; u < 2; ++u) {
            int lin  = u * 256 + t;
            int ch   = lin >> 7;
            int rem  = lin & 127;
            int row  = rem >> 5;
            int col4 = rem & 31;
            int grow = h0 - 1 + row;
            int ok   = (grow >= 0 && grow < HH);
            const float* src = xb + (size_t)(cb + ch) * PLANE
                             + (ok ? grow : 0) * WW + (col4 << 2);
            uint32_t dst = (uint32_t)__cvta_generic_to_shared(
                &xs[buf][ch][row * RSTR + 4 + (col4 << 2)]);
            cp_async16(dst, src, ok ? 16 : 0);
        }
    };

    load_stage(0, 0);
    cp_commit();

#pragma unroll 1
    for (int s = 0; s < NS; ++s) {
        int buf = s & 1;
        __syncthreads();
        if (s + 1 < NS) { load_stage(s + 1, buf ^ 1); cp_commit(); cp_wait<1>(); }
        else           { cp_wait<0>(); }
        __syncthreads();

        int cbase = c0 + s * STAGE;
#pragma unroll
        for (int ch = 0; ch < STAGE; ++ch) {
            const float* base = &xs[buf][ch][r * RSTR + 4 + w];
            ull acc0 = 0ull, acc1 = 0ull;
#pragma unroll
            for (int di = 0; di < 3; ++di) {
                const float* rp = base + di * RSTR;
                float xv[3] = { rp[-1], rp[0], rp[1] };
#pragma unroll
                for (int dj = 0; dj < 3; ++dj) {
                    int k = di * 3 + dj;
                    unsigned vu = __float_as_uint(xv[dj]);
                    ull vv;
                    asm("mov.b64 %0, {%1, %2};" : "=l"(vv) : "r"(vu), "r"(vu));
                    asm("fma.rn.f32x2 %0, %1, %2, %0;"
                        : "+l"(acc0) : "l"(wk0[k]), "l"(vv));
                    asm("fma.rn.f32x2 %0, %1, %2, %0;"
                        : "+l"(acc1) : "l"(wk1[k]), "l"(vv));
                }
            }
            float2* op = (float2*)(out + (((size_t)(b * CC + cbase + ch)) * H2
                                          + 2 * h) * W2);
            __stcs(&op[w], *(float2*)&acc0);
            __stcs(&op[(W2 / 2) + w], *(float2*)&acc1);
        }
    }
}

extern "C" void kernel_launch(void* const* d_in, const int* in_sizes, int n_in,
                              void* d_out, int out_size) {
    const float* x    = (const float*)d_in[0];
    const float* Woff = (const float*)d_in[1];
    const float* boff = (const float*)d_in[2];
    float* out = (float*)d_out;

    mean1_kernel<<<dim3(PLANE / 4 / 256, MG, BB), 256>>>(x);
    kern_kernel<<<dim3(W2 / 16, H2 / 16, BB), 256>>>(Woff, boff);
    carafe_kernel<<<dim3(CC / CPG, HH / 2, BB), 256>>>(x, out);
}